// round 12
// baseline (speedup 1.0000x reference)
#include <cuda_runtime.h>
#include <cstdint>

// ---------------------------------------------------------------------------
// MultiRectSDF: out[i] = min over 32 shapes of rotated-rect SDF at query[i].
//
// R12 = R8 codegen (unroll 4, no reg cap; best 35.0us @ regs 66) with:
//  * BLOCK=128: at 66 regs, 7 blocks/SM = 28 warps (43.8% occ) vs 3x256 = 24.
//    (R11 paired block128 with unroll 8, which grew regs to 72 and ate the
//    occupancy win; unroll stays at 4 here.)
//  * rot2(): the whole packed-rotation chain (2x fma.rn.f32x2 + pair split)
//    in ONE asm block, so ptxas can allocate the b64 as a register pair and
//    elide the mov.b64 splits. Measured alu% > fma% despite more fma-class
//    ops in the loop -> suspected surviving MOVs on the alu pipe.
//  * Branch-free epilogue (R11-verified exact):
//      minM < 0 => minSq = 0, so res = min(minM,0) + sqrt(minSq).
//
// Math (measured good since R5):
//   minSq = min_i (relu(dx)^2 + relu(dy)^2),  minM = min_i max(dx,dy)
// ---------------------------------------------------------------------------

static __device__ __forceinline__ unsigned long long pack2(float lo, float hi) {
    unsigned long long r;
    asm("mov.b64 %0, {%1, %2};" : "=l"(r) : "r"(__float_as_uint(lo)), "r"(__float_as_uint(hi)));
    return r;
}

// Full rotation chain for one packed coordinate:
//   R = fma2(a, x, fma2(b, y, c)), returning the two scalar halves.
// Single asm scope -> ptxas sees the b64 lifetime end at the split and can
// register-pair-allocate (r0,r1) onto it, eliding the MOVs.
static __device__ __forceinline__ void rot2(
    unsigned long long a, unsigned long long x,
    unsigned long long b, unsigned long long y,
    unsigned long long c, float& r0, float& r1) {
    asm("{\n\t"
        ".reg .b64 t, u;\n\t"
        "fma.rn.f32x2 t, %3, %4, %5;\n\t"
        "fma.rn.f32x2 u, %2, %6, t;\n\t"
        "mov.b64 {%0, %1}, u;\n\t"
        "}"
        : "=f"(r0), "=f"(r1)
        : "l"(a), "l"(b), "l"(y), "l"(c), "l"(x));
}

static __device__ __forceinline__ float fsqrt_approx(float x) {
    float y;
    asm("sqrt.approx.f32 %0, %1;" : "=f"(y) : "f"(x));
    return y;
}

struct __align__(16) ShapeConst {
    unsigned long long cP, sP, nsP, ntxP, ntyP;  // duplicated packed (v,v)
    float nrx, nry;                              // negated half-extents
};  // 48 bytes -> 3x LDS.128 per shape

static constexpr int NSHAPES = 32;
static constexpr int PTS_PER_THREAD = 8;   // 2x float4 in, 4 packed pairs
static constexpr int BLOCK = 128;          // finer occupancy quantization

__global__ __launch_bounds__(BLOCK)        // NO reg cap (R10 lesson)
void multirect_sdf_fast(const float* __restrict__ query,
                        const float* __restrict__ trans,
                        const float* __restrict__ rads,
                        const float* __restrict__ angles,
                        float* __restrict__ out) {
    __shared__ ShapeConst sc[NSHAPES];

    if (threadIdx.x < NSHAPES) {
        const int i = threadIdx.x;
        float s, c;
        __sincosf(angles[i], &s, &c);   // |angle| <= 0.1 -> ~1e-7 abs error
        const float tx = trans[2 * i + 0];
        const float ty = trans[2 * i + 1];
        sc[i].cP   = pack2(c, c);
        sc[i].sP   = pack2(s, s);
        sc[i].nsP  = pack2(-s, -s);
        sc[i].ntxP = pack2(-tx, -tx);
        sc[i].ntyP = pack2(-ty, -ty);
        sc[i].nrx  = -rads[2 * i + 0];
        sc[i].nry  = -rads[2 * i + 1];
    }
    __syncthreads();

    const int tid = blockIdx.x * BLOCK + threadIdx.x;

    // 8 points = 4x float4 (layout: x0 y0 x1 y1 ...)
    const float4* q4 = reinterpret_cast<const float4*>(query);
    unsigned long long X[4], Y[4];
#pragma unroll
    for (int k = 0; k < 4; k++) {
        const float4 q = q4[tid * 4 + k];
        X[k] = pack2(q.x, q.z);
        Y[k] = pack2(q.y, q.w);
    }

    float minSq[PTS_PER_THREAD], minM[PTS_PER_THREAD];
#pragma unroll
    for (int p = 0; p < PTS_PER_THREAD; p++) {
        minSq[p] = 3.0e38f;
        minM[p]  = 3.0e38f;
    }

#pragma unroll 4
    for (int i = 0; i < NSHAPES; i++) {
        const ShapeConst k = sc[i];   // 3x LDS.128, amortized over 4 pairs
#pragma unroll
        for (int pr = 0; pr < 4; pr++) {
            // Packed rotation + translation: 4 FFMA2 per point-pair.
            //   rx = c*qx - s*qy - tx ;  ry = s*qx + c*qy - ty
            float rx0, rx1, ry0, ry1;
            rot2(k.cP, X[pr], k.nsP, Y[pr], k.ntxP, rx0, rx1);
            rot2(k.sP, X[pr], k.cP,  Y[pr], k.ntyP, ry0, ry1);

            {
                const float dx = fabsf(rx0) + k.nrx;     // FADD with |src|
                const float dy = fabsf(ry0) + k.nry;
                const float mx = fmaxf(dx, 0.0f);
                const float my = fmaxf(dy, 0.0f);
                const float sq = fmaf(mx, mx, my * my);
                minSq[2 * pr + 0] = fminf(minSq[2 * pr + 0], sq);
                minM[2 * pr + 0]  = fminf(minM[2 * pr + 0], fmaxf(dx, dy));
            }
            {
                const float dx = fabsf(rx1) + k.nrx;
                const float dy = fabsf(ry1) + k.nry;
                const float mx = fmaxf(dx, 0.0f);
                const float my = fmaxf(dy, 0.0f);
                const float sq = fmaf(mx, mx, my * my);
                minSq[2 * pr + 1] = fminf(minSq[2 * pr + 1], sq);
                minM[2 * pr + 1]  = fminf(minM[2 * pr + 1], fmaxf(dx, dy));
            }
        }
    }

    // Branch-free epilogue: minM < 0 implies that shape contributed sq = 0,
    // so minSq = 0 and sqrt(minSq) = 0. Hence exactly:
    //   res = min(minM, 0) + sqrt(minSq)
    float res[PTS_PER_THREAD];
#pragma unroll
    for (int p = 0; p < PTS_PER_THREAD; p++) {
        res[p] = fminf(minM[p], 0.0f) + fsqrt_approx(minSq[p]);
    }

    float4* o4 = reinterpret_cast<float4*>(out);
    o4[tid * 2 + 0] = make_float4(res[0], res[1], res[2], res[3]);
    o4[tid * 2 + 1] = make_float4(res[4], res[5], res[6], res[7]);
}

// Generic fallback (any n, any shape count) — correctness safety net.
__global__ void multirect_sdf_generic(const float* __restrict__ query,
                                      const float* __restrict__ trans,
                                      const float* __restrict__ rads,
                                      const float* __restrict__ angles,
                                      float* __restrict__ out,
                                      int n, int ns) {
    const int i = blockIdx.x * blockDim.x + threadIdx.x;
    if (i >= n) return;
    const float qx = query[2 * i + 0];
    const float qy = query[2 * i + 1];
    float best = 3.0e38f;
    for (int s = 0; s < ns; s++) {
        float sn, c;
        __sincosf(angles[s], &sn, &c);
        const float rx = fmaf(c, qx, fmaf(-sn, qy, -trans[2 * s + 0]));
        const float ry = fmaf(sn, qx, fmaf(c, qy, -trans[2 * s + 1]));
        const float dx = fabsf(rx) - rads[2 * s + 0];
        const float dy = fabsf(ry) - rads[2 * s + 1];
        const float mx = fmaxf(dx, 0.0f);
        const float my = fmaxf(dy, 0.0f);
        const float o  = fsqrt_approx(fmaf(mx, mx, my * my));
        const float in = fminf(fmaxf(dx, dy), 0.0f);
        best = fminf(best, o + in);
    }
    out[i] = best;
}

extern "C" void kernel_launch(void* const* d_in, const int* in_sizes, int n_in,
                              void* d_out, int out_size) {
    const float* query  = (const float*)d_in[0];  // (N, 2) fp32
    const float* trans  = (const float*)d_in[1];  // (S, 2) fp32
    const float* rads   = (const float*)d_in[2];  // (S, 2) fp32
    const float* angles = (const float*)d_in[3];  // (S,)  fp32
    float* out = (float*)d_out;

    const int n  = in_sizes[0] / 2;
    const int ns = in_sizes[3];

    if (ns == NSHAPES && (n % PTS_PER_THREAD) == 0 &&
        ((n / PTS_PER_THREAD) % BLOCK) == 0) {
        const int threads = n / PTS_PER_THREAD;
        multirect_sdf_fast<<<threads / BLOCK, BLOCK>>>(query, trans, rads, angles, out);
    } else {
        const int blk = 256;
        multirect_sdf_generic<<<(n + blk - 1) / blk, blk>>>(query, trans, rads, angles,
                                                            out, n, ns);
    }
}

// round 13
// speedup vs baseline: 1.0042x; 1.0042x over previous
#include <cuda_runtime.h>
#include <cstdint>

// ---------------------------------------------------------------------------
// MultiRectSDF: out[i] = min over 32 shapes of rotated-rect SDF at query[i].
//
// R13 = R8 EXACT loop body (block 256, unroll 4, separate ffma2+unpack asm —
// the only form ptxas compiles cleanly; fused-asm variants R10/R12 exploded
// instruction count +55% -> 54us) with two additions:
//  1. One-shape-ahead software prefetch of ShapeConst: the 3x LDS.128 for
//     shape i+1 issue before shape i's compute, hiding the 29-cyc LDS
//     latency that otherwise lands at each unroll-window boundary.
//     (Targets the measured ~30% idle-issue gap; occupancy moves in R9-R12
//     never helped, so this attacks per-warp stalls instead.)
//  2. Branch-free epilogue (R11-verified exact):
//     minM < 0 => that shape had sq = 0 => minSq = 0, so
//     res = min(minM,0) + sqrt(minSq).
//
// Math (measured good since R5):
//   minSq = min_i (relu(dx)^2 + relu(dy)^2),  minM = min_i max(dx,dy)
// Rotation via packed fma.rn.f32x2; abs folded into scalar FADD.
// ---------------------------------------------------------------------------

static __device__ __forceinline__ unsigned long long pack2(float lo, float hi) {
    unsigned long long r;
    asm("mov.b64 %0, {%1, %2};" : "=l"(r) : "r"(__float_as_uint(lo)), "r"(__float_as_uint(hi)));
    return r;
}

static __device__ __forceinline__ void unpack2(unsigned long long v, float& lo, float& hi) {
    unsigned int a, b;
    asm("mov.b64 {%0, %1}, %2;" : "=r"(a), "=r"(b) : "l"(v));
    lo = __uint_as_float(a);
    hi = __uint_as_float(b);
}

static __device__ __forceinline__ unsigned long long ffma2(
    unsigned long long a, unsigned long long b, unsigned long long c) {
    unsigned long long d;
    asm("fma.rn.f32x2 %0, %1, %2, %3;" : "=l"(d) : "l"(a), "l"(b), "l"(c));
    return d;
}

static __device__ __forceinline__ float fsqrt_approx(float x) {
    float y;
    asm("sqrt.approx.f32 %0, %1;" : "=f"(y) : "f"(x));
    return y;
}

struct __align__(16) ShapeConst {
    unsigned long long cP, sP, nsP, ntxP, ntyP;  // duplicated packed (v,v)
    float nrx, nry;                              // negated half-extents
};  // 48 bytes -> 3x LDS.128 per shape

static constexpr int NSHAPES = 32;
static constexpr int PTS_PER_THREAD = 8;   // 2x float4 in, 4 packed pairs
static constexpr int BLOCK = 256;          // R8's measured-best config

__global__ __launch_bounds__(BLOCK)        // NO reg cap (R10 lesson)
void multirect_sdf_fast(const float* __restrict__ query,
                        const float* __restrict__ trans,
                        const float* __restrict__ rads,
                        const float* __restrict__ angles,
                        float* __restrict__ out) {
    __shared__ ShapeConst sc[NSHAPES];

    if (threadIdx.x < NSHAPES) {
        const int i = threadIdx.x;
        float s, c;
        __sincosf(angles[i], &s, &c);   // |angle| <= 0.1 -> ~1e-7 abs error
        const float tx = trans[2 * i + 0];
        const float ty = trans[2 * i + 1];
        sc[i].cP   = pack2(c, c);
        sc[i].sP   = pack2(s, s);
        sc[i].nsP  = pack2(-s, -s);
        sc[i].ntxP = pack2(-tx, -tx);
        sc[i].ntyP = pack2(-ty, -ty);
        sc[i].nrx  = -rads[2 * i + 0];
        sc[i].nry  = -rads[2 * i + 1];
    }
    __syncthreads();

    const int tid = blockIdx.x * BLOCK + threadIdx.x;

    // 8 points = 4x float4 (layout: x0 y0 x1 y1 ...)
    const float4* q4 = reinterpret_cast<const float4*>(query);
    unsigned long long X[4], Y[4];
#pragma unroll
    for (int k = 0; k < 4; k++) {
        const float4 q = q4[tid * 4 + k];
        X[k] = pack2(q.x, q.z);
        Y[k] = pack2(q.y, q.w);
    }

    float minSq[PTS_PER_THREAD], minM[PTS_PER_THREAD];
#pragma unroll
    for (int p = 0; p < PTS_PER_THREAD; p++) {
        minSq[p] = 3.0e38f;
        minM[p]  = 3.0e38f;
    }

    // Software-pipelined shape loop: k holds the current shape's constants,
    // kn prefetches the next shape's (wrap on the last iteration — harmless
    // extra load, avoids a branch). Each LDS batch gets a full shape's worth
    // of compute (~100 issue slots) to cover its 29-cycle latency.
    ShapeConst k = sc[0];
#pragma unroll 4
    for (int i = 0; i < NSHAPES; i++) {
        const ShapeConst kn = sc[(i + 1) & (NSHAPES - 1)];
#pragma unroll
        for (int pr = 0; pr < 4; pr++) {
            // Packed rotation + translation: 4 FFMA2 per point-pair.
            const unsigned long long RX = ffma2(k.cP, X[pr], ffma2(k.nsP, Y[pr], k.ntxP));
            const unsigned long long RY = ffma2(k.sP, X[pr], ffma2(k.cP, Y[pr], k.ntyP));
            float rx0, rx1, ry0, ry1;
            unpack2(RX, rx0, rx1);
            unpack2(RY, ry0, ry1);

            {
                const float dx = fabsf(rx0) + k.nrx;     // FADD with |src|
                const float dy = fabsf(ry0) + k.nry;
                const float mx = fmaxf(dx, 0.0f);
                const float my = fmaxf(dy, 0.0f);
                const float sq = fmaf(mx, mx, my * my);
                minSq[2 * pr + 0] = fminf(minSq[2 * pr + 0], sq);
                minM[2 * pr + 0]  = fminf(minM[2 * pr + 0], fmaxf(dx, dy));
            }
            {
                const float dx = fabsf(rx1) + k.nrx;
                const float dy = fabsf(ry1) + k.nry;
                const float mx = fmaxf(dx, 0.0f);
                const float my = fmaxf(dy, 0.0f);
                const float sq = fmaf(mx, mx, my * my);
                minSq[2 * pr + 1] = fminf(minSq[2 * pr + 1], sq);
                minM[2 * pr + 1]  = fminf(minM[2 * pr + 1], fmaxf(dx, dy));
            }
        }
        k = kn;   // register rename, free
    }

    // Branch-free epilogue: minM < 0 implies that shape contributed sq = 0,
    // so minSq = 0 and sqrt(minSq) = 0. Hence exactly:
    //   res = min(minM, 0) + sqrt(minSq)
    float res[PTS_PER_THREAD];
#pragma unroll
    for (int p = 0; p < PTS_PER_THREAD; p++) {
        res[p] = fminf(minM[p], 0.0f) + fsqrt_approx(minSq[p]);
    }

    float4* o4 = reinterpret_cast<float4*>(out);
    o4[tid * 2 + 0] = make_float4(res[0], res[1], res[2], res[3]);
    o4[tid * 2 + 1] = make_float4(res[4], res[5], res[6], res[7]);
}

// Generic fallback (any n, any shape count) — correctness safety net.
__global__ void multirect_sdf_generic(const float* __restrict__ query,
                                      const float* __restrict__ trans,
                                      const float* __restrict__ rads,
                                      const float* __restrict__ angles,
                                      float* __restrict__ out,
                                      int n, int ns) {
    const int i = blockIdx.x * blockDim.x + threadIdx.x;
    if (i >= n) return;
    const float qx = query[2 * i + 0];
    const float qy = query[2 * i + 1];
    float best = 3.0e38f;
    for (int s = 0; s < ns; s++) {
        float sn, c;
        __sincosf(angles[s], &sn, &c);
        const float rx = fmaf(c, qx, fmaf(-sn, qy, -trans[2 * s + 0]));
        const float ry = fmaf(sn, qx, fmaf(c, qy, -trans[2 * s + 1]));
        const float dx = fabsf(rx) - rads[2 * s + 0];
        const float dy = fabsf(ry) - rads[2 * s + 1];
        const float mx = fmaxf(dx, 0.0f);
        const float my = fmaxf(dy, 0.0f);
        const float o  = fsqrt_approx(fmaf(mx, mx, my * my));
        const float in = fminf(fmaxf(dx, dy), 0.0f);
        best = fminf(best, o + in);
    }
    out[i] = best;
}

extern "C" void kernel_launch(void* const* d_in, const int* in_sizes, int n_in,
                              void* d_out, int out_size) {
    const float* query  = (const float*)d_in[0];  // (N, 2) fp32
    const float* trans  = (const float*)d_in[1];  // (S, 2) fp32
    const float* rads   = (const float*)d_in[2];  // (S, 2) fp32
    const float* angles = (const float*)d_in[3];  // (S,)  fp32
    float* out = (float*)d_out;

    const int n  = in_sizes[0] / 2;
    const int ns = in_sizes[3];

    if (ns == NSHAPES && (n % PTS_PER_THREAD) == 0 &&
        ((n / PTS_PER_THREAD) % BLOCK) == 0) {
        const int threads = n / PTS_PER_THREAD;
        multirect_sdf_fast<<<threads / BLOCK, BLOCK>>>(query, trans, rads, angles, out);
    } else {
        const int blk = 256;
        multirect_sdf_generic<<<(n + blk - 1) / blk, blk>>>(query, trans, rads, angles,
                                                            out, n, ns);
    }
}

// round 14
// speedup vs baseline: 1.5458x; 1.5394x over previous
#include <cuda_runtime.h>
#include <cstdint>

// ---------------------------------------------------------------------------
// MultiRectSDF: out[i] = min over 32 shapes of rotated-rect SDF at query[i].
//
// R14 = R13 (software-pipelined shape constants + branch-free epilogue) with
// ONE change: __launch_bounds__(256, 3) -> reg ceiling 85.
//
// Why: R10/R12/R13 all failed the same way — when register demand exceeds
// ptxas's implicit occupancy target, it REMATERIALIZES (re-loads smem
// constants, +50% issued instructions, 54us). R13's prefetch demanded ~78
// regs; ptxas silently squeezed to 64 and re-loaded — the pipeline was
// compiled away, never tested. minBlocks=3 raises the budget to 85 regs,
// which fits both ShapeConst copies. Occupancy is unchanged vs best-known
// R8 (which also ran 3 blocks/SM at 66 regs).
//
// Math (measured good since R5):
//   minSq = min_i (relu(dx)^2 + relu(dy)^2),  minM = min_i max(dx,dy)
//   res = min(minM,0) + sqrt(minSq)   [exact: minM<0 => minSq=0]
// Rotation via packed fma.rn.f32x2 (separate asm form — the only form ptxas
// compiles cleanly); abs folded into scalar FADD.
// ---------------------------------------------------------------------------

static __device__ __forceinline__ unsigned long long pack2(float lo, float hi) {
    unsigned long long r;
    asm("mov.b64 %0, {%1, %2};" : "=l"(r) : "r"(__float_as_uint(lo)), "r"(__float_as_uint(hi)));
    return r;
}

static __device__ __forceinline__ void unpack2(unsigned long long v, float& lo, float& hi) {
    unsigned int a, b;
    asm("mov.b64 {%0, %1}, %2;" : "=r"(a), "=r"(b) : "l"(v));
    lo = __uint_as_float(a);
    hi = __uint_as_float(b);
}

static __device__ __forceinline__ unsigned long long ffma2(
    unsigned long long a, unsigned long long b, unsigned long long c) {
    unsigned long long d;
    asm("fma.rn.f32x2 %0, %1, %2, %3;" : "=l"(d) : "l"(a), "l"(b), "l"(c));
    return d;
}

static __device__ __forceinline__ float fsqrt_approx(float x) {
    float y;
    asm("sqrt.approx.f32 %0, %1;" : "=f"(y) : "f"(x));
    return y;
}

struct __align__(16) ShapeConst {
    unsigned long long cP, sP, nsP, ntxP, ntyP;  // duplicated packed (v,v)
    float nrx, nry;                              // negated half-extents
};  // 48 bytes -> 3x LDS.128 per shape

static constexpr int NSHAPES = 32;
static constexpr int PTS_PER_THREAD = 8;   // 2x float4 in, 4 packed pairs
static constexpr int BLOCK = 256;

__global__ __launch_bounds__(BLOCK, 3)     // reg ceiling 85: fits the pipeline
void multirect_sdf_fast(const float* __restrict__ query,
                        const float* __restrict__ trans,
                        const float* __restrict__ rads,
                        const float* __restrict__ angles,
                        float* __restrict__ out) {
    __shared__ ShapeConst sc[NSHAPES];

    if (threadIdx.x < NSHAPES) {
        const int i = threadIdx.x;
        float s, c;
        __sincosf(angles[i], &s, &c);   // |angle| <= 0.1 -> ~1e-7 abs error
        const float tx = trans[2 * i + 0];
        const float ty = trans[2 * i + 1];
        sc[i].cP   = pack2(c, c);
        sc[i].sP   = pack2(s, s);
        sc[i].nsP  = pack2(-s, -s);
        sc[i].ntxP = pack2(-tx, -tx);
        sc[i].ntyP = pack2(-ty, -ty);
        sc[i].nrx  = -rads[2 * i + 0];
        sc[i].nry  = -rads[2 * i + 1];
    }
    __syncthreads();

    const int tid = blockIdx.x * BLOCK + threadIdx.x;

    // 8 points = 4x float4 (layout: x0 y0 x1 y1 ...)
    const float4* q4 = reinterpret_cast<const float4*>(query);
    unsigned long long X[4], Y[4];
#pragma unroll
    for (int k = 0; k < 4; k++) {
        const float4 q = q4[tid * 4 + k];
        X[k] = pack2(q.x, q.z);
        Y[k] = pack2(q.y, q.w);
    }

    float minSq[PTS_PER_THREAD], minM[PTS_PER_THREAD];
#pragma unroll
    for (int p = 0; p < PTS_PER_THREAD; p++) {
        minSq[p] = 3.0e38f;
        minM[p]  = 3.0e38f;
    }

    // Software-pipelined shape loop: k holds shape i's constants in regs,
    // kn prefetches shape i+1's (wrap at the end — harmless extra load).
    // Each 3x LDS.128 batch gets a full shape of compute (~100 issue slots)
    // to cover its 29-cycle latency.
    ShapeConst k = sc[0];
#pragma unroll 4
    for (int i = 0; i < NSHAPES; i++) {
        const ShapeConst kn = sc[(i + 1) & (NSHAPES - 1)];
#pragma unroll
        for (int pr = 0; pr < 4; pr++) {
            // Packed rotation + translation: 4 FFMA2 per point-pair.
            const unsigned long long RX = ffma2(k.cP, X[pr], ffma2(k.nsP, Y[pr], k.ntxP));
            const unsigned long long RY = ffma2(k.sP, X[pr], ffma2(k.cP, Y[pr], k.ntyP));
            float rx0, rx1, ry0, ry1;
            unpack2(RX, rx0, rx1);
            unpack2(RY, ry0, ry1);

            {
                const float dx = fabsf(rx0) + k.nrx;     // FADD with |src|
                const float dy = fabsf(ry0) + k.nry;
                const float mx = fmaxf(dx, 0.0f);
                const float my = fmaxf(dy, 0.0f);
                const float sq = fmaf(mx, mx, my * my);
                minSq[2 * pr + 0] = fminf(minSq[2 * pr + 0], sq);
                minM[2 * pr + 0]  = fminf(minM[2 * pr + 0], fmaxf(dx, dy));
            }
            {
                const float dx = fabsf(rx1) + k.nrx;
                const float dy = fabsf(ry1) + k.nry;
                const float mx = fmaxf(dx, 0.0f);
                const float my = fmaxf(dy, 0.0f);
                const float sq = fmaf(mx, mx, my * my);
                minSq[2 * pr + 1] = fminf(minSq[2 * pr + 1], sq);
                minM[2 * pr + 1]  = fminf(minM[2 * pr + 1], fmaxf(dx, dy));
            }
        }
        k = kn;   // register rename, free
    }

    // Branch-free epilogue (exact): res = min(minM,0) + sqrt(minSq)
    float res[PTS_PER_THREAD];
#pragma unroll
    for (int p = 0; p < PTS_PER_THREAD; p++) {
        res[p] = fminf(minM[p], 0.0f) + fsqrt_approx(minSq[p]);
    }

    float4* o4 = reinterpret_cast<float4*>(out);
    o4[tid * 2 + 0] = make_float4(res[0], res[1], res[2], res[3]);
    o4[tid * 2 + 1] = make_float4(res[4], res[5], res[6], res[7]);
}

// Generic fallback (any n, any shape count) — correctness safety net.
__global__ void multirect_sdf_generic(const float* __restrict__ query,
                                      const float* __restrict__ trans,
                                      const float* __restrict__ rads,
                                      const float* __restrict__ angles,
                                      float* __restrict__ out,
                                      int n, int ns) {
    const int i = blockIdx.x * blockDim.x + threadIdx.x;
    if (i >= n) return;
    const float qx = query[2 * i + 0];
    const float qy = query[2 * i + 1];
    float best = 3.0e38f;
    for (int s = 0; s < ns; s++) {
        float sn, c;
        __sincosf(angles[s], &sn, &c);
        const float rx = fmaf(c, qx, fmaf(-sn, qy, -trans[2 * s + 0]));
        const float ry = fmaf(sn, qx, fmaf(c, qy, -trans[2 * s + 1]));
        const float dx = fabsf(rx) - rads[2 * s + 0];
        const float dy = fabsf(ry) - rads[2 * s + 1];
        const float mx = fmaxf(dx, 0.0f);
        const float my = fmaxf(dy, 0.0f);
        const float o  = fsqrt_approx(fmaf(mx, mx, my * my));
        const float in = fminf(fmaxf(dx, dy), 0.0f);
        best = fminf(best, o + in);
    }
    out[i] = best;
}

extern "C" void kernel_launch(void* const* d_in, const int* in_sizes, int n_in,
                              void* d_out, int out_size) {
    const float* query  = (const float*)d_in[0];  // (N, 2) fp32
    const float* trans  = (const float*)d_in[1];  // (S, 2) fp32
    const float* rads   = (const float*)d_in[2];  // (S, 2) fp32
    const float* angles = (const float*)d_in[3];  // (S,)  fp32
    float* out = (float*)d_out;

    const int n  = in_sizes[0] / 2;
    const int ns = in_sizes[3];

    if (ns == NSHAPES && (n % PTS_PER_THREAD) == 0 &&
        ((n / PTS_PER_THREAD) % BLOCK) == 0) {
        const int threads = n / PTS_PER_THREAD;
        multirect_sdf_fast<<<threads / BLOCK, BLOCK>>>(query, trans, rads, angles, out);
    } else {
        const int blk = 256;
        multirect_sdf_generic<<<(n + blk - 1) / blk, blk>>>(query, trans, rads, angles,
                                                            out, n, ns);
    }
}

// round 15
// speedup vs baseline: 1.6231x; 1.0500x over previous
#include <cuda_runtime.h>
#include <cstdint>

// ---------------------------------------------------------------------------
// MultiRectSDF: out[i] = min over 32 shapes of rotated-rect SDF at query[i].
//
// R15 = R14's exact codegen (software-pipelined shape constants, branch-free
// epilogue, explicit register budget — the combination that finally compiled
// without rematerialization, regs=72, 34.9us) with ONE launch-shape change:
//   BLOCK 256 -> 128, __launch_bounds__(128, 6)  (reg ceiling 85, demand 72)
// At 72 regs, 128-thread blocks pack 7/SM = 28 warps (vs 24) and grid=2048
// gives two near-perfect waves (13.84 blocks/SM over 7 concurrent) instead
// of R14's ragged 3 rounds (6.92 over 3). Same inner instructions.
//
// Accumulated model: fma pipe w/ FFMA2 dual-pump/RF-banking is the structural
// floor (~31-33us); this round recovers wave-tail + warp-coverage slack.
//
// Math (measured exact since R5/R11):
//   minSq = min_i (relu(dx)^2 + relu(dy)^2),  minM = min_i max(dx,dy)
//   res = min(minM,0) + sqrt(minSq)    [minM<0 => minSq=0]
// ---------------------------------------------------------------------------

static __device__ __forceinline__ unsigned long long pack2(float lo, float hi) {
    unsigned long long r;
    asm("mov.b64 %0, {%1, %2};" : "=l"(r) : "r"(__float_as_uint(lo)), "r"(__float_as_uint(hi)));
    return r;
}

static __device__ __forceinline__ void unpack2(unsigned long long v, float& lo, float& hi) {
    unsigned int a, b;
    asm("mov.b64 {%0, %1}, %2;" : "=r"(a), "=r"(b) : "l"(v));
    lo = __uint_as_float(a);
    hi = __uint_as_float(b);
}

static __device__ __forceinline__ unsigned long long ffma2(
    unsigned long long a, unsigned long long b, unsigned long long c) {
    unsigned long long d;
    asm("fma.rn.f32x2 %0, %1, %2, %3;" : "=l"(d) : "l"(a), "l"(b), "l"(c));
    return d;
}

static __device__ __forceinline__ float fsqrt_approx(float x) {
    float y;
    asm("sqrt.approx.f32 %0, %1;" : "=f"(y) : "f"(x));
    return y;
}

struct __align__(16) ShapeConst {
    unsigned long long cP, sP, nsP, ntxP, ntyP;  // duplicated packed (v,v)
    float nrx, nry;                              // negated half-extents
};  // 48 bytes -> 3x LDS.128 per shape

static constexpr int NSHAPES = 32;
static constexpr int PTS_PER_THREAD = 8;   // 2x float4 in, 4 packed pairs
static constexpr int BLOCK = 128;          // 7 blocks/SM @ 72 regs -> 28 warps

__global__ __launch_bounds__(BLOCK, 6)     // ceiling 85 regs: fits demand 72,
                                           // no remat (R13->R14 lesson)
void multirect_sdf_fast(const float* __restrict__ query,
                        const float* __restrict__ trans,
                        const float* __restrict__ rads,
                        const float* __restrict__ angles,
                        float* __restrict__ out) {
    __shared__ ShapeConst sc[NSHAPES];

    if (threadIdx.x < NSHAPES) {
        const int i = threadIdx.x;
        float s, c;
        __sincosf(angles[i], &s, &c);   // |angle| <= 0.1 -> ~1e-7 abs error
        const float tx = trans[2 * i + 0];
        const float ty = trans[2 * i + 1];
        sc[i].cP   = pack2(c, c);
        sc[i].sP   = pack2(s, s);
        sc[i].nsP  = pack2(-s, -s);
        sc[i].ntxP = pack2(-tx, -tx);
        sc[i].ntyP = pack2(-ty, -ty);
        sc[i].nrx  = -rads[2 * i + 0];
        sc[i].nry  = -rads[2 * i + 1];
    }
    __syncthreads();

    const int tid = blockIdx.x * BLOCK + threadIdx.x;

    // 8 points = 4x float4 (layout: x0 y0 x1 y1 ...)
    const float4* q4 = reinterpret_cast<const float4*>(query);
    unsigned long long X[4], Y[4];
#pragma unroll
    for (int k = 0; k < 4; k++) {
        const float4 q = q4[tid * 4 + k];
        X[k] = pack2(q.x, q.z);
        Y[k] = pack2(q.y, q.w);
    }

    float minSq[PTS_PER_THREAD], minM[PTS_PER_THREAD];
#pragma unroll
    for (int p = 0; p < PTS_PER_THREAD; p++) {
        minSq[p] = 3.0e38f;
        minM[p]  = 3.0e38f;
    }

    // Software-pipelined shape loop: k holds shape i's constants in regs,
    // kn prefetches shape i+1's (wrap at the end — harmless extra load).
    ShapeConst k = sc[0];
#pragma unroll 4
    for (int i = 0; i < NSHAPES; i++) {
        const ShapeConst kn = sc[(i + 1) & (NSHAPES - 1)];
#pragma unroll
        for (int pr = 0; pr < 4; pr++) {
            // Packed rotation + translation: 4 FFMA2 per point-pair.
            const unsigned long long RX = ffma2(k.cP, X[pr], ffma2(k.nsP, Y[pr], k.ntxP));
            const unsigned long long RY = ffma2(k.sP, X[pr], ffma2(k.cP, Y[pr], k.ntyP));
            float rx0, rx1, ry0, ry1;
            unpack2(RX, rx0, rx1);
            unpack2(RY, ry0, ry1);

            {
                const float dx = fabsf(rx0) + k.nrx;     // FADD with |src|
                const float dy = fabsf(ry0) + k.nry;
                const float mx = fmaxf(dx, 0.0f);
                const float my = fmaxf(dy, 0.0f);
                const float sq = fmaf(mx, mx, my * my);
                minSq[2 * pr + 0] = fminf(minSq[2 * pr + 0], sq);
                minM[2 * pr + 0]  = fminf(minM[2 * pr + 0], fmaxf(dx, dy));
            }
            {
                const float dx = fabsf(rx1) + k.nrx;
                const float dy = fabsf(ry1) + k.nry;
                const float mx = fmaxf(dx, 0.0f);
                const float my = fmaxf(dy, 0.0f);
                const float sq = fmaf(mx, mx, my * my);
                minSq[2 * pr + 1] = fminf(minSq[2 * pr + 1], sq);
                minM[2 * pr + 1]  = fminf(minM[2 * pr + 1], fmaxf(dx, dy));
            }
        }
        k = kn;   // register rename, free
    }

    // Branch-free epilogue (exact): res = min(minM,0) + sqrt(minSq)
    float res[PTS_PER_THREAD];
#pragma unroll
    for (int p = 0; p < PTS_PER_THREAD; p++) {
        res[p] = fminf(minM[p], 0.0f) + fsqrt_approx(minSq[p]);
    }

    float4* o4 = reinterpret_cast<float4*>(out);
    o4[tid * 2 + 0] = make_float4(res[0], res[1], res[2], res[3]);
    o4[tid * 2 + 1] = make_float4(res[4], res[5], res[6], res[7]);
}

// Generic fallback (any n, any shape count) — correctness safety net.
__global__ void multirect_sdf_generic(const float* __restrict__ query,
                                      const float* __restrict__ trans,
                                      const float* __restrict__ rads,
                                      const float* __restrict__ angles,
                                      float* __restrict__ out,
                                      int n, int ns) {
    const int i = blockIdx.x * blockDim.x + threadIdx.x;
    if (i >= n) return;
    const float qx = query[2 * i + 0];
    const float qy = query[2 * i + 1];
    float best = 3.0e38f;
    for (int s = 0; s < ns; s++) {
        float sn, c;
        __sincosf(angles[s], &sn, &c);
        const float rx = fmaf(c, qx, fmaf(-sn, qy, -trans[2 * s + 0]));
        const float ry = fmaf(sn, qx, fmaf(c, qy, -trans[2 * s + 1]));
        const float dx = fabsf(rx) - rads[2 * s + 0];
        const float dy = fabsf(ry) - rads[2 * s + 1];
        const float mx = fmaxf(dx, 0.0f);
        const float my = fmaxf(dy, 0.0f);
        const float o  = fsqrt_approx(fmaf(mx, mx, my * my));
        const float in = fminf(fmaxf(dx, dy), 0.0f);
        best = fminf(best, o + in);
    }
    out[i] = best;
}

extern "C" void kernel_launch(void* const* d_in, const int* in_sizes, int n_in,
                              void* d_out, int out_size) {
    const float* query  = (const float*)d_in[0];  // (N, 2) fp32
    const float* trans  = (const float*)d_in[1];  // (S, 2) fp32
    const float* rads   = (const float*)d_in[2];  // (S, 2) fp32
    const float* angles = (const float*)d_in[3];  // (S,)  fp32
    float* out = (float*)d_out;

    const int n  = in_sizes[0] / 2;
    const int ns = in_sizes[3];

    if (ns == NSHAPES && (n % PTS_PER_THREAD) == 0 &&
        ((n / PTS_PER_THREAD) % BLOCK) == 0) {
        const int threads = n / PTS_PER_THREAD;
        multirect_sdf_fast<<<threads / BLOCK, BLOCK>>>(query, trans, rads, angles, out);
    } else {
        const int blk = 256;
        multirect_sdf_generic<<<(n + blk - 1) / blk, blk>>>(query, trans, rads, angles,
                                                            out, n, ns);
    }
}